// round 13
// baseline (speedup 1.0000x reference)
#include <cuda_runtime.h>
#include <cuda_bf16.h>
#include <math.h>
#include <cstdint>

// ---------------- problem constants ----------------
#define NBATCH 8
#define NCHAN  64
#define NH     48
#define NW     48
#define NQ     8192
#define BQ     (NBATCH * NQ)      // 65536 queries
#define NROWS  (4 * BQ)           // 262144 MLP rows (4 shifts)
#define NPIX   (NBATCH * NH * NW) // 18432 distinct pixels
#define KREAL  596
#define HID    256
#define OUTD   27

typedef __nv_bfloat16 bf16;

// ---------------- device globals (allocation-free rule) ----------------
__device__ bf16  g_Fh [NBATCH * NH * NW * NCHAN];   // feat NHWC hi plane (2.25 MB)
__device__ bf16  g_Fl [NBATCH * NH * NW * NCHAN];
__device__ float g_P  [(size_t)NPIX * HID];         // per-pixel patch@W0 (18.9 MB, L2-resident)
__device__ bf16  g_W0ph[HID * 576];                 // w0^T rows 0..575, K-permuted (k'=p*64+c)
__device__ bf16  g_W0pl[HID * 576];
__device__ bf16  g_WTh[HID * 32];                   // w0^T tail rows 576..607 (rel+cell+pad)
__device__ bf16  g_WTl[HID * 32];
__device__ bf16  g_W1h[HID * HID];
__device__ bf16  g_W1l[HID * HID];
__device__ bf16  g_W2h[HID * HID];
__device__ bf16  g_W2l[HID * HID];
__device__ bf16  g_W3h[HID * HID];
__device__ bf16  g_W3l[HID * HID];
__device__ float g_W4t[OUTD * 260];                 // w4^T, row-padded to 260 fp32

// ---------------- PTX helpers ----------------
__device__ __forceinline__ uint32_t smem_u32(const void* p) {
    uint32_t a;
    asm("{ .reg .u64 t; cvta.to.shared.u64 t, %1; cvt.u32.u64 %0, t; }" : "=r"(a) : "l"(p));
    return a;
}
__device__ __forceinline__ void cpa16(uint32_t s, const void* g) {
    asm volatile("cp.async.cg.shared.global [%0], [%1], 16;" :: "r"(s), "l"(g));
}
__device__ __forceinline__ void cpa16z(uint32_t s, const void* g, uint32_t n) {
    asm volatile("cp.async.cg.shared.global [%0], [%1], 16, %2;" :: "r"(s), "l"(g), "r"(n));
}
#define CP_COMMIT() asm volatile("cp.async.commit_group;" ::: "memory")
template<int N>
__device__ __forceinline__ void cp_wait() {
    asm volatile("cp.async.wait_group %0;" :: "n"(N) : "memory");
}
__device__ __forceinline__ void ldsm4(uint32_t (&r)[4], uint32_t addr) {
    asm volatile("ldmatrix.sync.aligned.m8n8.x4.shared.b16 {%0,%1,%2,%3}, [%4];"
        : "=r"(r[0]), "=r"(r[1]), "=r"(r[2]), "=r"(r[3]) : "r"(addr));
}
__device__ __forceinline__ void mma16816(float (&c)[4], const uint32_t (&a)[4],
                                         uint32_t b0, uint32_t b1) {
    asm volatile("mma.sync.aligned.m16n8k16.row.col.f32.bf16.bf16.f32 "
        "{%0,%1,%2,%3}, {%4,%5,%6,%7}, {%8,%9}, {%0,%1,%2,%3};"
        : "+f"(c[0]), "+f"(c[1]), "+f"(c[2]), "+f"(c[3])
        : "r"(a[0]), "r"(a[1]), "r"(a[2]), "r"(a[3]), "r"(b0), "r"(b1));
}
__device__ __forceinline__ void split_bf16(float v, bf16& h, bf16& l) {
    h = __float2bfloat16(v);
    l = __float2bfloat16(v - __bfloat162float(h));
}

// ---------------- smem layout: mlp_fused (one CTA/SM) ----------------
#define ASTRIDE  528
#define ABUF_LO  67584                 // lo plane offset inside A-buf
#define G_STAGE  20480                 // gather stage (Ah 10240 + Al 10240), overlays A-buf
#define OFF_BST  135168                // B stream: 2 stages x (Bh 20480 + Bl 20480)
#define BSTAGE   40960
#define OFF_W4   135168                // final phase: w4^T overlay (27 x 260 fp32)
#define OFF_HC   163264                // final phase: Hc (32 x 260 fp32)
#define OFF_BIAS 217088                // 256 f32
#define OFF_AREA 218112                // 128 f32
#define OFF_PIX  218624                // 128 i32
#define SMEM_TOTAL 219136

// ---------------- smem layout: p_gemm ----------------
#define PG_BST   40960                 // gather stages at 0 (2 x 20480), B at 40960 (2 x 40960)
#define PG_SMEM  122880

// ---------------- weight prep ----------------
__global__ void prep_weights(const float* __restrict__ w0, const float* __restrict__ w1,
                             const float* __restrict__ w2, const float* __restrict__ w3,
                             const float* __restrict__ w4)
{
    int idx = blockIdx.x * 256 + threadIdx.x;      // grid 608 -> up to 155648
    if (idx < HID * 576) {
        int n = idx / 576, kp = idx - n * 576;
        int p = kp >> 6, c = kp & 63;
        int ko = c * 9 + p;
        split_bf16(w0[ko * HID + n], g_W0ph[idx], g_W0pl[idx]);
    }
    if (idx < HID * 32) {
        int n = idx >> 5, j = idx & 31;
        float v = (j < 20) ? w0[(576 + j) * HID + n] : 0.0f;
        split_bf16(v, g_WTh[idx], g_WTl[idx]);
    }
    if (idx < HID * HID) {
        int n = idx >> 8, k = idx & 255;
        split_bf16(w1[k * HID + n], g_W1h[idx], g_W1l[idx]);
        split_bf16(w2[k * HID + n], g_W2h[idx], g_W2l[idx]);
        split_bf16(w3[k * HID + n], g_W3h[idx], g_W3l[idx]);
    }
    if (idx < OUTD * HID) {
        int o = idx >> 8, k = idx & 255;
        g_W4t[o * 260 + k] = w4[k * OUTD + o];
    }
}

// ---------------- feat -> NHWC bf16 hi/lo planes ----------------
__global__ void feat_prep(const float* __restrict__ feat)
{
    int idx = blockIdx.x * 256 + threadIdx.x;
    if (idx >= NBATCH * NH * NW * NCHAN) return;
    int t = idx;
    int c = t & 63; t >>= 6;
    int w = t % 48; t /= 48;
    int h = t % 48; int b = t / 48;
    float v = feat[(((size_t)b * 64 + c) * 48 + h) * 48 + w];
    split_bf16(v, g_Fh[idx], g_Fl[idx]);
}

// ---------------- coordinate helper ----------------
__device__ __forceinline__ void calc_rc(const float* cp, int s, int& row, int& col)
{
    const float SP  = (float)( 1.0 / 48.0 + 1e-6);
    const float SN  = (float)(-1.0 / 48.0 + 1e-6);
    const float CLO = (float)(-1.0 + 1e-6);
    const float CHI = (float)( 1.0 - 1e-6);
    float cx = cp[8] + ((s & 2) ? SP : SN);
    float cy = cp[9] + ((s & 1) ? SP : SN);
    cx = fminf(fmaxf(cx, CLO), CHI);
    cy = fminf(fmaxf(cy, CLO), CHI);
    row = (int)rintf((cx + 1.0f) * 24.0f - 0.5f);
    col = (int)rintf((cy + 1.0f) * 24.0f - 0.5f);
    row = min(max(row, 0), NH - 1);
    col = min(max(col, 0), NW - 1);
}

// ---------------- MMA step: 3-term bf16 split, warp tile 32x64 ----------------
#define MMA_STEP(AHB, ALB, AOFF, AKO, BHB, BLB, BKO)                                 \
    do {                                                                             \
        uint32_t ah[2][4], bh[4][4];                                                 \
        _Pragma("unroll")                                                            \
        for (int i = 0; i < 2; i++) ldsm4(ah[i], (AHB) + (AOFF)[i] + (AKO));         \
        _Pragma("unroll")                                                            \
        for (int j = 0; j < 4; j++) ldsm4(bh[j], (BHB) + boff[j] + (BKO));           \
        _Pragma("unroll")                                                            \
        for (int i = 0; i < 2; i++)                                                  \
            _Pragma("unroll")                                                        \
            for (int j = 0; j < 4; j++)                                              \
                _Pragma("unroll")                                                    \
                for (int h = 0; h < 2; h++)                                          \
                    mma16816(acc[i][j * 2 + h], ah[i], bh[j][2 * h], bh[j][2 * h + 1]); \
        uint32_t al[2][4];                                                           \
        _Pragma("unroll")                                                            \
        for (int i = 0; i < 2; i++) ldsm4(al[i], (ALB) + (AOFF)[i] + (AKO));         \
        _Pragma("unroll")                                                            \
        for (int i = 0; i < 2; i++)                                                  \
            _Pragma("unroll")                                                        \
            for (int j = 0; j < 4; j++)                                              \
                _Pragma("unroll")                                                    \
                for (int h = 0; h < 2; h++)                                          \
                    mma16816(acc[i][j * 2 + h], al[i], bh[j][2 * h], bh[j][2 * h + 1]); \
        uint32_t bl[4][4];                                                           \
        _Pragma("unroll")                                                            \
        for (int j = 0; j < 4; j++) ldsm4(bl[j], (BLB) + boff[j] + (BKO));           \
        _Pragma("unroll")                                                            \
        for (int i = 0; i < 2; i++)                                                  \
            _Pragma("unroll")                                                        \
            for (int j = 0; j < 4; j++)                                              \
                _Pragma("unroll")                                                    \
                for (int h = 0; h < 2; h++)                                          \
                    mma16816(acc[i][j * 2 + h], ah[i], bl[j][2 * h], bl[j][2 * h + 1]); \
    } while (0)

#define ZERO_ACC()                                                                   \
    _Pragma("unroll")                                                                \
    for (int i = 0; i < 2; i++)                                                      \
        _Pragma("unroll")                                                            \
        for (int j = 0; j < 8; j++)                                                  \
            _Pragma("unroll")                                                        \
            for (int r = 0; r < 4; r++) acc[i][j][r] = 0.0f;

#define FRAG_OFFSETS()                                                               \
    uint32_t aoff0[2], aoffA[2], boff[4];                                            \
    _Pragma("unroll")                                                                \
    for (int i = 0; i < 2; i++) {                                                    \
        int rb = wm * 32 + i * 16 + (lane & 15);                                     \
        aoff0[i] = (uint32_t)(rb * 80)      + ((lane >> 4) << 4);                    \
        aoffA[i] = (uint32_t)(rb * ASTRIDE) + ((lane >> 4) << 4);                    \
    }                                                                                \
    _Pragma("unroll")                                                                \
    for (int j = 0; j < 4; j++) {                                                    \
        int rb = wn * 64 + j * 16 + (lane & 7) + ((lane >> 4) << 3);                 \
        boff[j] = (uint32_t)(rb * 80) + (((lane >> 3) & 1) << 4);                    \
    }

// epilogue: relu(acc+bias), split hi/lo, write into smem A-buffer
#define EPI_TO_SMEM()                                                                \
    _Pragma("unroll")                                                                \
    for (int i = 0; i < 2; i++) {                                                    \
        const int r0 = wm * 32 + i * 16 + (lane >> 2);                               \
        _Pragma("unroll")                                                            \
        for (int jj = 0; jj < 8; jj++) {                                             \
            const int ncl = wn * 64 + jj * 8 + (lane & 3) * 2;                       \
            const float bz0 = biasS[ncl], bz1 = biasS[ncl + 1];                      \
            _Pragma("unroll")                                                        \
            for (int p = 0; p < 2; p++) {                                            \
                float v0 = fmaxf(acc[i][jj][2 * p + 0] + bz0, 0.0f);                 \
                float v1 = fmaxf(acc[i][jj][2 * p + 1] + bz1, 0.0f);                 \
                bf16 h0, l0, h1, l1;                                                 \
                split_bf16(v0, h0, l0);                                              \
                split_bf16(v1, h1, l1);                                              \
                const int row = r0 + p * 8;                                          \
                *(__nv_bfloat162*)(smem + row * ASTRIDE + ncl * 2)                   \
                    = __nv_bfloat162(h0, h1);                                        \
                *(__nv_bfloat162*)(smem + ABUF_LO + row * ASTRIDE + ncl * 2)         \
                    = __nv_bfloat162(l0, l1);                                        \
            }                                                                        \
        }                                                                            \
    }

// ---------------- p_gemm: P[pix] = unfold(feat)[pix] @ W0[:576]^T (fp32 out) ----
__global__ void __launch_bounds__(512, 1) p_gemm()
{
    extern __shared__ char smem[];
    const int tid  = threadIdx.x;
    const int lane = tid & 31;
    const int wid  = tid >> 5;
    const int wm   = wid & 3;
    const int wn   = wid >> 2;
    const int row0 = blockIdx.x * 128;
    const uint32_t sb = smem_u32(smem);

    // per-thread gather identity (4 threads per pixel row)
    const int cr = tid >> 2;
    const int sg = tid & 3;
    const int pix = row0 + cr;
    const int pb  = pix / 2304;
    const int prem = pix - pb * 2304;
    const int ph  = prem / 48;
    const int pw  = prem - ph * 48;

    uint32_t aoff0[2], boff[4];
    #pragma unroll
    for (int i = 0; i < 2; i++) {
        int rb = wm * 32 + i * 16 + (lane & 15);
        aoff0[i] = (uint32_t)(rb * 80) + ((lane >> 4) << 4);
    }
    #pragma unroll
    for (int j = 0; j < 4; j++) {
        int rb = wn * 64 + j * 16 + (lane & 7) + ((lane >> 4) << 3);
        boff[j] = (uint32_t)(rb * 80) + (((lane >> 3) & 1) << 4);
    }

    const int br  = tid >> 1;
    const int b2s = (tid & 1) << 1;

    auto load0 = [&](int c, int ps) {
        uint32_t bb = sb + PG_BST + (uint32_t)ps * BSTAGE;
        uint32_t bo = (uint32_t)(br * 80) + ((uint32_t)b2s << 4);
        const bf16* gbh = g_W0ph + (size_t)br * 576 + c * 32 + b2s * 8;
        const bf16* gbl = g_W0pl + (size_t)br * 576 + c * 32 + b2s * 8;
        cpa16(bb + bo,              gbh);
        cpa16(bb + bo + 16,         gbh + 8);
        cpa16(bb + 20480 + bo,      gbl);
        cpa16(bb + 20480 + bo + 16, gbl + 8);
        uint32_t ab = sb + (uint32_t)ps * G_STAGE;
        uint32_t ao = (uint32_t)(cr * 80) + ((uint32_t)sg << 4);
        int p  = c >> 1;
        int hh = ph + p / 3 - 1;
        int ww = pw + p % 3 - 1;
        uint32_t ok = (((unsigned)hh < 48u) && ((unsigned)ww < 48u)) ? 16u : 0u;
        int hc = min(max(hh, 0), 47), wc = min(max(ww, 0), 47);
        size_t gi = ((((size_t)pb * 48 + hc) * 48 + wc) << 6)
                  + ((c & 1) << 5) + (sg << 3);
        cpa16z(ab + ao,         g_Fh + gi, ok);
        cpa16z(ab + 10240 + ao, g_Fl + gi, ok);
    };

    float acc[2][8][4];
    ZERO_ACC();

    load0(0, 0);
    CP_COMMIT();
    for (int c = 0; c < 18; c++) {
        const int st = c & 1;
        if (c + 1 < 18) { load0(c + 1, st ^ 1); CP_COMMIT(); cp_wait<1>(); }
        else            { cp_wait<0>(); }
        __syncthreads();
        uint32_t ahb = sb + (uint32_t)st * G_STAGE;
        uint32_t alb = ahb + 10240;
        uint32_t bhb = sb + PG_BST + (uint32_t)st * BSTAGE;
        uint32_t blb = bhb + 20480;
        MMA_STEP(ahb, alb, aoff0, 0u,  bhb, blb, 0u);
        MMA_STEP(ahb, alb, aoff0, 32u, bhb, blb, 32u);
        __syncthreads();
    }

    // fp32 epilogue -> g_P
    #pragma unroll
    for (int i = 0; i < 2; i++) {
        const int r0 = wm * 32 + i * 16 + (lane >> 2);
        #pragma unroll
        for (int jj = 0; jj < 8; jj++) {
            const int ncl = wn * 64 + jj * 8 + (lane & 3) * 2;
            #pragma unroll
            for (int p = 0; p < 2; p++) {
                const int prow = row0 + r0 + p * 8;
                *(float2*)(g_P + (size_t)prow * HID + ncl)
                    = make_float2(acc[i][jj][2 * p + 0], acc[i][jj][2 * p + 1]);
            }
        }
    }
}

// ---------------- fused MLP: correction + layers 1-3 + blend + final GEMM --------
// Row order: grow = bq*4 + s  (all 4 shifts of a query adjacent -> CTA-local blend)
__global__ void __launch_bounds__(512, 1)
mlp_fused(const float* __restrict__ coord, const float* __restrict__ cell,
          const float* __restrict__ b0, const float* __restrict__ b1,
          const float* __restrict__ b2, const float* __restrict__ b3,
          const float* __restrict__ b4, float* __restrict__ out)
{
    extern __shared__ char smem[];
    const int tid  = threadIdx.x;
    const int lane = tid & 31;
    const int wid  = tid >> 5;
    const int wm   = wid & 3;        // M group (32 rows)
    const int wn   = wid >> 2;       // N group (64 cols)
    const int row0 = blockIdx.x * 128;
    const int bq0  = blockIdx.x * 32;

    float* biasS = (float*)(smem + OFF_BIAS);
    float* areaS = (float*)(smem + OFF_AREA);
    int*   pixS  = (int*)(smem + OFF_PIX);
    const uint32_t sb = smem_u32(smem);

    // ---- gather identity for this thread (4 threads per row) ----
    const int cr = tid >> 2;         // local row 0..127
    const int sg = tid & 3;          // segment 0..3
    const int grow = row0 + cr;
    const int gbq  = grow >> 2;
    const int gs   = grow & 3;
    const float* cpr = coord + (size_t)gbq * 18;
    int irow, icol;
    calc_rc(cpr, gs, irow, icol);
    const float qcr_r = (float)(2 * irow + 1) / 48.0f - 1.0f;
    const float qcc_r = (float)(2 * icol + 1) / 48.0f - 1.0f;

    // ---- per-row area + pixel index (1 thread per row) ----
    if (tid < 128) {
        int gr = row0 + tid;
        int bq = gr >> 2, s = gr & 3;
        int bb = bq >> 13;
        const float* cp = coord + (size_t)bq * 18;
        int r, c;
        calc_rc(cp, s, r, c);
        float qr = (float)(2 * r + 1) / 48.0f - 1.0f;
        float qc = (float)(2 * c + 1) / 48.0f - 1.0f;
        float ax = (cp[0] - qr) * 2304.0f;
        float ay = (cp[1] - qc);
        areaS[tid] = fabsf(ax * ay) + 1e-9f;
        pixS[tid]  = (bb * 48 + r) * 48 + c;
    }
    if (tid < 256) biasS[tid] = b0[tid];

    FRAG_OFFSETS();

    const int br  = tid >> 1;        // B row 0..255
    const int b2s = (tid & 1) << 1;

    auto loadB = [&](const bf16* Wh, const bf16* Wl, int c, int ps) {
        uint32_t bb = sb + OFF_BST + (uint32_t)ps * BSTAGE;
        uint32_t bo = (uint32_t)(br * 80) + ((uint32_t)b2s << 4);
        const bf16* gbh = Wh + (size_t)br * HID + c * 32 + b2s * 8;
        const bf16* gbl = Wl + (size_t)br * HID + c * 32 + b2s * 8;
        cpa16(bb + bo,              gbh);
        cpa16(bb + bo + 16,         gbh + 8);
        cpa16(bb + 20480 + bo,      gbl);
        cpa16(bb + 20480 + bo + 16, gbl + 8);
    };

    float acc[2][8][4];
    ZERO_ACC();

    // ================= layer 0 correction: K=32 (rel 18 + cell 2 + pad) ==========
    {
        // B = WT (stride 32)
        uint32_t bb = sb + OFF_BST;
        uint32_t bo = (uint32_t)(br * 80) + ((uint32_t)b2s << 4);
        const bf16* gbh = g_WTh + br * 32 + b2s * 8;
        const bf16* gbl = g_WTl + br * 32 + b2s * 8;
        cpa16(bb + bo,              gbh);
        cpa16(bb + bo + 16,         gbh + 8);
        cpa16(bb + 20480 + bo,      gbl);
        cpa16(bb + 20480 + bo + 16, gbl + 8);
        // A tail values -> gather stage 0 (hi/lo)
        bf16* dh = (bf16*)(smem + cr * 80);
        bf16* dl = dh + 5120;
        #pragma unroll
        for (int t = 0; t < 8; t++) {
            int l = sg * 8 + t;
            float v;
            if (l < 18)      { float cv = cpr[l]; v = (l & 1) ? (cv - qcc_r) : (cv - qcr_r) * 2304.0f; }
            else if (l < 20) { v = cell[(size_t)gbq * 2 + (l - 18)] * 48.0f; }
            else             { v = 0.0f; }
            bf16 h, lo;
            split_bf16(v, h, lo);
            dh[l] = h; dl[l] = lo;
        }
        CP_COMMIT();
        cp_wait<0>();
        __syncthreads();
        uint32_t bhb = sb + OFF_BST;
        uint32_t blb = bhb + 20480;
        MMA_STEP(sb, sb + 10240, aoff0, 0u,  bhb, blb, 0u);
        MMA_STEP(sb, sb + 10240, aoff0, 32u, bhb, blb, 32u);
        __syncthreads();
    }

    // ---- epilogue 0: acc + P[pix] + b0, relu, split -> A-buf ----
    #pragma unroll
    for (int i = 0; i < 2; i++) {
        const int r0 = wm * 32 + i * 16 + (lane >> 2);
        const int px0 = pixS[r0];
        const int px1 = pixS[r0 + 8];
        #pragma unroll
        for (int jj = 0; jj < 8; jj++) {
            const int ncl = wn * 64 + jj * 8 + (lane & 3) * 2;
            const float bz0 = biasS[ncl], bz1 = biasS[ncl + 1];
            #pragma unroll
            for (int p = 0; p < 2; p++) {
                const int px = p ? px1 : px0;
                float2 pv = *(const float2*)(g_P + (size_t)px * HID + ncl);
                float v0 = fmaxf(acc[i][jj][2 * p + 0] + pv.x + bz0, 0.0f);
                float v1 = fmaxf(acc[i][jj][2 * p + 1] + pv.y + bz1, 0.0f);
                bf16 h0, l0, h1, l1;
                split_bf16(v0, h0, l0);
                split_bf16(v1, h1, l1);
                const int row = r0 + p * 8;
                *(__nv_bfloat162*)(smem + row * ASTRIDE + ncl * 2)
                    = __nv_bfloat162(h0, h1);
                *(__nv_bfloat162*)(smem + ABUF_LO + row * ASTRIDE + ncl * 2)
                    = __nv_bfloat162(l0, l1);
            }
        }
    }
    __syncthreads();

    // ================= layers 1-3: A resident in smem =================
    const bf16* WH[3] = { g_W1h, g_W2h, g_W3h };
    const bf16* WL[3] = { g_W1l, g_W2l, g_W3l };
    const float* BB[3] = { b1, b2, b3 };

    for (int L = 0; L < 3; L++) {
        if (tid < 256) biasS[tid] = BB[L][tid];
        ZERO_ACC();
        loadB(WH[L], WL[L], 0, 0);
        CP_COMMIT();
        for (int c = 0; c < 8; c++) {
            const int st = c & 1;
            if (c + 1 < 8) { loadB(WH[L], WL[L], c + 1, st ^ 1); CP_COMMIT(); cp_wait<1>(); }
            else           { cp_wait<0>(); }
            __syncthreads();
            uint32_t ahb = sb;
            uint32_t alb = sb + ABUF_LO;
            uint32_t bhb = sb + OFF_BST + (uint32_t)st * BSTAGE;
            uint32_t blb = bhb + 20480;
            const uint32_t ako = (uint32_t)(c << 6);
            MMA_STEP(ahb, alb, aoffA, ako,       bhb, blb, 0u);
            MMA_STEP(ahb, alb, aoffA, ako + 32u, bhb, blb, 32u);
            __syncthreads();
        }
        EPI_TO_SMEM();
        __syncthreads();
    }

    // ================= stage w4^T into the dead B-stream region =================
    float* w4S = (float*)(smem + OFF_W4);
    float* hcS = (float*)(smem + OFF_HC);
    for (int i = tid; i < OUTD * HID; i += 512) {
        int o = i >> 8, k = i & 255;
        w4S[o * 260 + k] = g_W4t[o * 260 + k];
    }

    // ================= blend across shifts -> smem Hc (fp32) =================
    for (int idx = tid; idx < 32 * HID; idx += 512) {
        const int q = idx >> 8, k = idx & 255;
        float a0 = areaS[q * 4 + 0];
        float a1 = areaS[q * 4 + 1];
        float a2 = areaS[q * 4 + 2];
        float a3 = areaS[q * 4 + 3];
        float inv = 1.0f / (a0 + a1 + a2 + a3);
        float hc = 0.0f;
        #pragma unroll
        for (int s = 0; s < 4; s++) {
            const int row = q * 4 + s;
            float h = __bfloat162float(*(const bf16*)(smem + row * ASTRIDE + k * 2))
                    + __bfloat162float(*(const bf16*)(smem + ABUF_LO + row * ASTRIDE + k * 2));
            float w = (s == 0) ? a3 : (s == 1) ? a2 : (s == 2) ? a1 : a0;
            hc += h * w;
        }
        hcS[q * 260 + k] = hc * inv;
    }
    __syncthreads();

    // ================= final 256 -> 27 GEMM: warp q, lane o =================
    #pragma unroll
    for (int rep = 0; rep < 2; rep++) {
        const int q = wid * 2 + rep;
        if (lane < OUTD) {
            const float* hq = hcS + q * 260;
            const float* wo = w4S + lane * 260;
            float s = 0.0f;
            #pragma unroll 4
            for (int k = 0; k < HID; k += 4) {
                float4 h4 = *(const float4*)(hq + k);   // warp-broadcast
                float4 w4v = *(const float4*)(wo + k);
                s += h4.x * w4v.x + h4.y * w4v.y + h4.z * w4v.z + h4.w * w4v.w;
            }
            out[(size_t)(bq0 + q) * OUTD + lane] = s + __ldg(&b4[lane]);
        }
    }
}

// ---------------- launch ----------------
extern "C" void kernel_launch(void* const* d_in, const int* in_sizes, int n_in,
                              void* d_out, int out_size)
{
    const float* feat  = (const float*)d_in[0];
    const float* coord = (const float*)d_in[1];
    const float* cell  = (const float*)d_in[2];
    const float* w0 = (const float*)d_in[3];
    const float* b0 = (const float*)d_in[4];
    const float* w1 = (const float*)d_in[5];
    const float* b1 = (const float*)d_in[6];
    const float* w2 = (const float*)d_in[7];
    const float* b2 = (const float*)d_in[8];
    const float* w3 = (const float*)d_in[9];
    const float* b3 = (const float*)d_in[10];
    const float* w4 = (const float*)d_in[11];
    const float* b4 = (const float*)d_in[12];
    float* out = (float*)d_out;

    cudaFuncSetAttribute(p_gemm,    cudaFuncAttributeMaxDynamicSharedMemorySize, PG_SMEM);
    cudaFuncSetAttribute(mlp_fused, cudaFuncAttributeMaxDynamicSharedMemorySize, SMEM_TOTAL);

    prep_weights<<<608, 256>>>(w0, w1, w2, w3, w4);
    feat_prep   <<<(NBATCH * NH * NW * NCHAN + 255) / 256, 256>>>(feat);

    p_gemm<<<NPIX / 128, 512, PG_SMEM>>>();                              // 144 CTAs, ~1 wave

    mlp_fused<<<NROWS / 128, 512, SMEM_TOTAL>>>(coord, cell, b0, b1, b2, b3, b4, out);
}